// round 2
// baseline (speedup 1.0000x reference)
#include <cuda_runtime.h>
#include <cuda_bf16.h>

// ---------------------------------------------------------------------------
// SelfAttention: GroupNorm(32) -> QKV -> softmax(QK^T*s) V -> out proj -> +x
// Shapes: b=4, c=512, h=w=64, N=4096 tokens per batch.
// fp32 128x128x16 SGEMM (8x8 microtile) + transpose/softmax helpers.
// ---------------------------------------------------------------------------

#define B_ 4
#define C_ 512
#define N_ 4096            // h*w
#define G_ 32
#define CPG 16             // channels per group
#define SCALE_ 0.044194173824159216f  // 1/sqrt(512)

// ---------------- scratch (device globals; allocation-free) ----------------
// Buffer reuse: o (attn out) overwrites q, o2 (out-proj) overwrites k.
__device__ float g_t [(long)B_ * N_ * C_];   // normalized tokens [b,n,c]
__device__ float g_q [(long)B_ * N_ * C_];   // q, later attn output o
__device__ float g_k [(long)B_ * N_ * C_];   // k, later out-proj o2
__device__ float g_v [(long)B_ * N_ * C_];
__device__ float g_s [(long)B_ * N_ * N_];   // scores [b,n,m]  (256 MB)
__device__ float g_stats[B_ * G_ * 2];       // mean, rstd interleaved

// ---------------------------------------------------------------------------
// GroupNorm stats: one block per (b,g); 65536 contiguous floats per group.
// ---------------------------------------------------------------------------
__global__ void gn_stats_kernel(const float* __restrict__ x,
                                float* __restrict__ stats) {
    const long CNT = (long)CPG * N_;                 // 65536
    const float4* p = (const float4*)(x + (long)blockIdx.x * CNT);
    int tid = threadIdx.x;
    float s = 0.f, q = 0.f;
    for (int i = tid; i < CNT / 4; i += 256) {
        float4 v = p[i];
        s += v.x + v.y + v.z + v.w;
        q += v.x * v.x + v.y * v.y + v.z * v.z + v.w * v.w;
    }
    __shared__ float rs[256], rq[256];
    rs[tid] = s; rq[tid] = q;
    __syncthreads();
    for (int st = 128; st > 0; st >>= 1) {
        if (tid < st) { rs[tid] += rs[tid + st]; rq[tid] += rq[tid + st]; }
        __syncthreads();
    }
    if (tid == 0) {
        float mean = rs[0] / 65536.f;
        float var  = rq[0] / 65536.f - mean * mean;
        stats[blockIdx.x * 2 + 0] = mean;
        stats[blockIdx.x * 2 + 1] = rsqrtf(var + 1e-6f);
    }
}

// ---------------------------------------------------------------------------
// Apply GN + transpose [b,c,n] -> token-major t[b,n,c] via 32x32 smem tile.
// grid: (N/32, C/32, B), block (32,8)
// ---------------------------------------------------------------------------
__global__ void gn_apply_kernel(const float* __restrict__ x,
                                const float* __restrict__ gamma,
                                const float* __restrict__ beta,
                                const float* __restrict__ stats,
                                float* __restrict__ t) {
    __shared__ float tile[32][33];
    int b  = blockIdx.z;
    int n0 = blockIdx.x * 32;
    int c0 = blockIdx.y * 32;
    int tx = threadIdx.x, ty = threadIdx.y;
#pragma unroll
    for (int i = 0; i < 4; i++) {
        int c = c0 + ty + i * 8;
        int g = c >> 4;
        float mean = stats[(b * G_ + g) * 2 + 0];
        float rstd = stats[(b * G_ + g) * 2 + 1];
        float v = x[((long)(b * C_ + c)) * N_ + n0 + tx];
        tile[ty + i * 8][tx] = (v - mean) * rstd * gamma[c] + beta[c];
    }
    __syncthreads();
#pragma unroll
    for (int i = 0; i < 4; i++) {
        int n = n0 + ty + i * 8;
        t[((long)b * N_ + n) * C_ + c0 + tx] = tile[tx][ty + i * 8];
    }
}

// ---------------------------------------------------------------------------
// Tiled fp32 SGEMM.  C[M,N] = scale * A[M,K] * op(B) + bias
//   BT=true : B is [N,K] row-major (NT) -> C = A B^T
//   BT=false: B is [K,N] row-major (NN)
// BM=BN=128, BK=16, 256 threads, 8x8 microtile, float4 global loads.
// All dims are multiples of the tile sizes. grid.z = batch.
// ---------------------------------------------------------------------------
#define BM 128
#define BN 128
#define BK 16

template <bool BT>
__global__ __launch_bounds__(256)
void gemm_kernel(const float* __restrict__ A,
                 const float* __restrict__ B,
                 float* __restrict__ C,
                 int M, int N, int K,
                 long strideA, long strideB, long strideC,
                 const float* __restrict__ bias, float scale) {
    __shared__ float As[BK][BM + 4];
    __shared__ float Bs[BK][BN + 4];

    A += (long)blockIdx.z * strideA;
    B += (long)blockIdx.z * strideB;
    C += (long)blockIdx.z * strideC;

    const int bm = blockIdx.y * BM;
    const int bn = blockIdx.x * BN;
    const int tid = threadIdx.x;        // 0..255
    const int tx = tid & 15;            // col group (0..15) -> 8 cols each
    const int ty = tid >> 4;            // row group (0..15) -> 8 rows each

    float acc[8][8] = {};

    for (int k0 = 0; k0 < K; k0 += BK) {
        // ---- load A tile: 128 rows x 16 cols, transposed into As[k][m] ----
#pragma unroll
        for (int i = 0; i < 2; i++) {
            int idx = tid + i * 256;            // 0..511 float4 slots
            int r  = idx >> 2;                  // row 0..127
            int c4 = idx & 3;                   // which float4 in the row
            float4 va = *(const float4*)&A[(long)(bm + r) * K + k0 + c4 * 4];
            As[c4 * 4 + 0][r] = va.x;
            As[c4 * 4 + 1][r] = va.y;
            As[c4 * 4 + 2][r] = va.z;
            As[c4 * 4 + 3][r] = va.w;
        }
        // ---- load B tile ----
        if (BT) {
            // B[N,K]: 128 rows x 16 cols, transposed into Bs[k][n]
#pragma unroll
            for (int i = 0; i < 2; i++) {
                int idx = tid + i * 256;
                int r  = idx >> 2;
                int c4 = idx & 3;
                float4 vb = *(const float4*)&B[(long)(bn + r) * K + k0 + c4 * 4];
                Bs[c4 * 4 + 0][r] = vb.x;
                Bs[c4 * 4 + 1][r] = vb.y;
                Bs[c4 * 4 + 2][r] = vb.z;
                Bs[c4 * 4 + 3][r] = vb.w;
            }
        } else {
            // B[K,N]: 16 rows x 128 cols, direct float4 copy
#pragma unroll
            for (int i = 0; i < 2; i++) {
                int idx = tid + i * 256;        // 0..511
                int r  = idx >> 5;              // row 0..15
                int c4 = idx & 31;              // float4 col 0..31
                float4 vb = *(const float4*)&B[(long)(k0 + r) * N + bn + c4 * 4];
                *(float4*)&Bs[r][c4 * 4] = vb;
            }
        }
        __syncthreads();

#pragma unroll
        for (int kk = 0; kk < BK; kk++) {
            float ra[8], rb[8];
            *(float4*)&ra[0] = *(const float4*)&As[kk][ty * 8];
            *(float4*)&ra[4] = *(const float4*)&As[kk][ty * 8 + 4];
            *(float4*)&rb[0] = *(const float4*)&Bs[kk][tx * 8];
            *(float4*)&rb[4] = *(const float4*)&Bs[kk][tx * 8 + 4];
#pragma unroll
            for (int i = 0; i < 8; i++)
#pragma unroll
                for (int j = 0; j < 8; j++)
                    acc[i][j] += ra[i] * rb[j];
        }
        __syncthreads();
    }

#pragma unroll
    for (int i = 0; i < 8; i++) {
        int r = bm + ty * 8 + i;
#pragma unroll
        for (int j = 0; j < 8; j++) {
            int cc = bn + tx * 8 + j;
            float v = acc[i][j] * scale;
            if (bias) v += bias[cc];
            C[(long)r * N + cc] = v;
        }
    }
}

// ---------------------------------------------------------------------------
// Row softmax in-place over scores [b][n][m], one block per row.
// ---------------------------------------------------------------------------
__global__ void softmax_kernel(float* __restrict__ S) {
    float4* row = (float4*)(S + ((long)blockIdx.y * N_ + blockIdx.x) * N_);
    int tid = threadIdx.x;
    __shared__ float red[256];

    float m = -1e30f;
    for (int i = tid; i < N_ / 4; i += 256) {
        float4 v = row[i];
        m = fmaxf(m, fmaxf(fmaxf(v.x, v.y), fmaxf(v.z, v.w)));
    }
    red[tid] = m;
    __syncthreads();
    for (int s = 128; s > 0; s >>= 1) {
        if (tid < s) red[tid] = fmaxf(red[tid], red[tid + s]);
        __syncthreads();
    }
    m = red[0];
    __syncthreads();

    float sum = 0.f;
    for (int i = tid; i < N_ / 4; i += 256) {
        float4 v = row[i];
        v.x = __expf(v.x - m); v.y = __expf(v.y - m);
        v.z = __expf(v.z - m); v.w = __expf(v.w - m);
        row[i] = v;
        sum += v.x + v.y + v.z + v.w;
    }
    red[tid] = sum;
    __syncthreads();
    for (int s = 128; s > 0; s >>= 1) {
        if (tid < s) red[tid] += red[tid + s];
        __syncthreads();
    }
    float inv = 1.0f / red[0];
    for (int i = tid; i < N_ / 4; i += 256) {
        float4 v = row[i];
        v.x *= inv; v.y *= inv; v.z *= inv; v.w *= inv;
        row[i] = v;
    }
}

// ---------------------------------------------------------------------------
// Residual + transpose: out[b,c,n] = o2[b,n,c] + x[b,c,n]
// grid: (N/32, C/32, B), block (32,8)
// ---------------------------------------------------------------------------
__global__ void resid_kernel(const float* __restrict__ o2,
                             const float* __restrict__ x,
                             float* __restrict__ out) {
    __shared__ float tile[32][33];
    int b  = blockIdx.z;
    int n0 = blockIdx.x * 32;
    int c0 = blockIdx.y * 32;
    int tx = threadIdx.x, ty = threadIdx.y;
#pragma unroll
    for (int i = 0; i < 4; i++) {
        int n = n0 + ty + i * 8;
        tile[ty + i * 8][tx] = o2[((long)b * N_ + n) * C_ + c0 + tx];
    }
    __syncthreads();
#pragma unroll
    for (int i = 0; i < 4; i++) {
        int c = c0 + ty + i * 8;
        long idx = ((long)(b * C_ + c)) * N_ + n0 + tx;
        out[idx] = tile[tx][ty + i * 8] + x[idx];
    }
}

// ---------------------------------------------------------------------------
// Launcher
// ---------------------------------------------------------------------------
extern "C" void kernel_launch(void* const* d_in, const int* in_sizes, int n_in,
                              void* d_out, int out_size) {
    const float* x     = (const float*)d_in[0];
    const float* gamma = (const float*)d_in[1];
    const float* beta  = (const float*)d_in[2];
    const float* wq_w  = (const float*)d_in[3];
    const float* wq_b  = (const float*)d_in[4];
    const float* wk_w  = (const float*)d_in[5];
    const float* wk_b  = (const float*)d_in[6];
    const float* wv_w  = (const float*)d_in[7];
    const float* wv_b  = (const float*)d_in[8];
    const float* ow_w  = (const float*)d_in[9];
    const float* ow_b  = (const float*)d_in[10];
    float* out = (float*)d_out;

    float *t, *q, *k, *v, *s, *stats;
    cudaGetSymbolAddress((void**)&t,     g_t);
    cudaGetSymbolAddress((void**)&q,     g_q);
    cudaGetSymbolAddress((void**)&k,     g_k);
    cudaGetSymbolAddress((void**)&v,     g_v);
    cudaGetSymbolAddress((void**)&s,     g_s);
    cudaGetSymbolAddress((void**)&stats, g_stats);

    float* o  = q;   // attn output overwrites q (dead after scores)
    float* o2 = k;   // out-proj output overwrites k (dead after scores)

    const long tokStride = (long)N_ * C_;        // per-batch stride for q/k/v/o
    const long scStride  = (long)N_ * N_;        // per-batch stride for scores
    const int  MT = B_ * N_;                     // 16384 flattened tokens

    // 1) GroupNorm stats
    gn_stats_kernel<<<B_ * G_, 256>>>(x, stats);

    // 2) Normalize + transpose to token-major
    gn_apply_kernel<<<dim3(N_ / 32, C_ / 32, B_), dim3(32, 8)>>>(
        x, gamma, beta, stats, t);

    // 3) QKV projections: [16384,512] x [512,512]^T (+bias)
    dim3 gqkv(C_ / BN, MT / BM, 1);
    gemm_kernel<true><<<gqkv, 256>>>(t, wq_w, q, MT, C_, C_, 0, 0, 0, wq_b, 1.f);
    gemm_kernel<true><<<gqkv, 256>>>(t, wk_w, k, MT, C_, C_, 0, 0, 0, wk_b, 1.f);
    gemm_kernel<true><<<gqkv, 256>>>(t, wv_w, v, MT, C_, C_, 0, 0, 0, wv_b, 1.f);

    // 4) Scores = scale * Q K^T  (batched)
    gemm_kernel<true><<<dim3(N_ / BN, N_ / BM, B_), 256>>>(
        q, k, s, N_, N_, C_, tokStride, tokStride, scStride, nullptr, SCALE_);

    // 5) Row softmax
    softmax_kernel<<<dim3(N_, B_), 256>>>(s);

    // 6) O = P V  (batched, NN)  -- writes into o (= old q buffer)
    gemm_kernel<false><<<dim3(C_ / BN, N_ / BM, B_), 256>>>(
        s, v, o, N_, C_, N_, scStride, tokStride, tokStride, nullptr, 1.f);

    // 7) Out projection (+bias) -- writes into o2 (= old k buffer)
    gemm_kernel<true><<<gqkv, 256>>>(o, ow_w, o2, MT, C_, C_, 0, 0, 0, ow_b, 1.f);

    // 8) Residual + transpose back to [b,c,h,w]
    resid_kernel<<<dim3(N_ / 32, C_ / 32, B_), dim3(32, 8)>>>(o2, x, out);
}

// round 5
// speedup vs baseline: 5.2698x; 5.2698x over previous
#include <cuda_runtime.h>
#include <cuda_bf16.h>
#include <stdint.h>

// ---------------------------------------------------------------------------
// SelfAttention: GroupNorm(32) -> QKV -> softmax(QK^T*s) V -> out proj -> +x
// b=4, c=512, h=w=64, N=4096. GEMMs: bf16 mma.sync.m16n8k16 (fp32 accum),
// ldmatrix fragments, cp.async double-buffered SMEM. Plain sm_103 ISA only.
// ---------------------------------------------------------------------------

#define B_ 4
#define C_ 512
#define N_ 4096
#define G_ 32
#define CPG 16
#define SCALE_ 0.044194173824159216f   // 1/sqrt(512)
#define CC (C_ * C_)

// ---------------- scratch (device globals; allocation-free) ----------------
__device__ __nv_bfloat16 gb_t [(long)B_ * N_ * C_];   // GN tokens  [b,n,c]
__device__ __nv_bfloat16 gb_q [(long)B_ * N_ * C_];
__device__ __nv_bfloat16 gb_k [(long)B_ * N_ * C_];
__device__ __nv_bfloat16 gb_v [(long)B_ * N_ * C_];
__device__ __nv_bfloat16 gb_vt[(long)B_ * N_ * C_];   // V^T [b,c,n]
__device__ __nv_bfloat16 gb_o [(long)B_ * N_ * C_];   // attn out [b,n,c]
__device__ __nv_bfloat16 gb_p [(long)B_ * N_ * N_];   // probs bf16 (128MB)
__device__ float         g_s  [(long)B_ * N_ * N_];   // scores fp32; reused as o2
__device__ __nv_bfloat16 gb_w [4 * CC];               // bf16 weights: q,k,v,out
__device__ float         g_stats[B_ * G_ * 2];

// ======================= PTX helpers =======================================
__device__ __forceinline__ uint32_t smem_u32(const void* p) {
    uint32_t a;
    asm("{ .reg .u64 t; cvta.to.shared.u64 t, %1; cvt.u32.u64 %0, t; }"
        : "=r"(a) : "l"(p));
    return a;
}
__device__ __forceinline__ void ldm_x4(uint32_t* r, uint32_t addr) {
    asm volatile("ldmatrix.sync.aligned.m8n8.x4.shared.b16 {%0,%1,%2,%3}, [%4];"
                 : "=r"(r[0]), "=r"(r[1]), "=r"(r[2]), "=r"(r[3]) : "r"(addr));
}
__device__ __forceinline__ void mma16816(float* c, const uint32_t* a,
                                         const uint32_t* b) {
    asm volatile(
        "mma.sync.aligned.m16n8k16.row.col.f32.bf16.bf16.f32 "
        "{%0,%1,%2,%3}, {%4,%5,%6,%7}, {%8,%9}, {%0,%1,%2,%3};"
        : "+f"(c[0]), "+f"(c[1]), "+f"(c[2]), "+f"(c[3])
        : "r"(a[0]), "r"(a[1]), "r"(a[2]), "r"(a[3]), "r"(b[0]), "r"(b[1]));
}
__device__ __forceinline__ void cp16(uint32_t dst, const void* src) {
    asm volatile("cp.async.cg.shared.global [%0], [%1], 16;"
                 :: "r"(dst), "l"(src));
}
#define CP_COMMIT() asm volatile("cp.async.commit_group;" ::: "memory")
#define CP_WAIT(n)  asm volatile("cp.async.wait_group %0;" :: "n"(n) : "memory")

// ======================= bf16 mma.sync NT GEMM =============================
// D[M,N] = scale * A[M,K] B[N,K]^T (+bias). Tiles: 128x128x32.
// 8 warps, warp tile 64x32. SMEM rows padded to 80B (conflict-free ldmatrix).
#define TM 128
#define TN 128
#define TK 32
#define ROWB 80                       // bytes per padded smem row (64 data)
#define ATILE (TM * ROWB)             // 10240
#define SBUF  (2 * ATILE)             // one buffer: A + B

template <bool OBF>
__global__ __launch_bounds__(256, 2)
void gemm_bf16_kernel(const __nv_bfloat16* __restrict__ A,
                      const __nv_bfloat16* __restrict__ Bm,
                      void* __restrict__ Cout,
                      int Nn, int K, long sA, long sB, long sC,
                      const float* __restrict__ bias, float scale) {
    __shared__ char smem[2 * SBUF];
    const uint32_t sb = smem_u32(smem);
    const int tid  = threadIdx.x;
    const int lane = tid & 31;
    const int wid  = tid >> 5;
    const int wm   = (wid & 1) * 64;      // warp m-offset
    const int wn   = (wid >> 1) * 32;     // warp n-offset

    A  += (long)blockIdx.z * sA + (long)blockIdx.y * TM * K;
    Bm += (long)blockIdx.z * sB + (long)blockIdx.x * TN * K;

    // load thread mapping: 512 uint4 per tile, 2 per thread
    const int lr0 = tid >> 2;             // row for idx = tid
    const int lc0 = (tid & 3) * 16;       // byte col
    const int nch = K / TK;

    // prologue: chunk 0 -> buffer 0
    {
        const char* Ap = (const char*)A;
        const char* Bp = (const char*)Bm;
#pragma unroll
        for (int i = 0; i < 2; i++) {
            int r = lr0 + i * 64;
            cp16(sb + r * ROWB + lc0,         Ap + (long)r * (K * 2) + lc0);
            cp16(sb + ATILE + r * ROWB + lc0, Bp + (long)r * (K * 2) + lc0);
        }
        CP_COMMIT();
    }

    float acc[4][4][4] = {};

    for (int c = 0; c < nch; c++) {
        const int buf = c & 1;
        if (c + 1 < nch) {
            const char* Ap = (const char*)A  + (c + 1) * (TK * 2);
            const char* Bp = (const char*)Bm + (c + 1) * (TK * 2);
            const uint32_t d = sb + (buf ^ 1) * SBUF;
#pragma unroll
            for (int i = 0; i < 2; i++) {
                int r = lr0 + i * 64;
                cp16(d + r * ROWB + lc0,         Ap + (long)r * (K * 2) + lc0);
                cp16(d + ATILE + r * ROWB + lc0, Bp + (long)r * (K * 2) + lc0);
            }
            CP_COMMIT();
            CP_WAIT(1);
        } else {
            CP_WAIT(0);
        }
        __syncthreads();

        const uint32_t Ab = sb + buf * SBUF;
        const uint32_t Bb = Ab + ATILE;
#pragma unroll
        for (int ks = 0; ks < 2; ks++) {
            const int kb = ks * 32;       // byte offset of k16 step
            uint32_t afr[4][4], bfr[4][2];
#pragma unroll
            for (int mi = 0; mi < 4; mi++) {
                int row = wm + mi * 16 + (lane & 15);
                ldm_x4(afr[mi], Ab + row * ROWB + kb + (lane >> 4) * 16);
            }
#pragma unroll
            for (int njp = 0; njp < 2; njp++) {
                uint32_t r4[4];
                int nrow = wn + njp * 16 + ((lane >> 4) * 8) + (lane & 7);
                int kbb  = kb + ((lane >> 3) & 1) * 16;
                ldm_x4(r4, Bb + nrow * ROWB + kbb);
                bfr[njp * 2 + 0][0] = r4[0]; bfr[njp * 2 + 0][1] = r4[1];
                bfr[njp * 2 + 1][0] = r4[2]; bfr[njp * 2 + 1][1] = r4[3];
            }
#pragma unroll
            for (int mi = 0; mi < 4; mi++)
#pragma unroll
                for (int nj = 0; nj < 4; nj++)
                    mma16816(acc[mi][nj], afr[mi], bfr[nj]);
        }
        __syncthreads();
    }

    // ---- epilogue ----
    const int bmr = blockIdx.y * TM + wm;
    const int bnc = blockIdx.x * TN + wn;
    const long cb = (long)blockIdx.z * sC;
#pragma unroll
    for (int mi = 0; mi < 4; mi++) {
#pragma unroll
        for (int h = 0; h < 2; h++) {
            const int row = bmr + mi * 16 + (lane >> 2) + 8 * h;
#pragma unroll
            for (int nj = 0; nj < 4; nj++) {
                const int col = bnc + nj * 8 + (lane & 3) * 2;
                float v0 = acc[mi][nj][2 * h + 0] * scale;
                float v1 = acc[mi][nj][2 * h + 1] * scale;
                if (bias) { v0 += __ldg(&bias[col]); v1 += __ldg(&bias[col + 1]); }
                if (OBF) {
                    __nv_bfloat162 bp = __floats2bfloat162_rn(v0, v1);
                    *(uint32_t*)((__nv_bfloat16*)Cout + cb + (long)row * Nn + col) =
                        *reinterpret_cast<uint32_t*>(&bp);
                } else {
                    *(float2*)((float*)Cout + cb + (long)row * Nn + col) =
                        make_float2(v0, v1);
                }
            }
        }
    }
}

// ======================= small kernels =====================================
__global__ void gn_stats_kernel(const float* __restrict__ x, float* __restrict__ st) {
    const long CNT = (long)CPG * N_;
    const float4* p = (const float4*)(x + (long)blockIdx.x * CNT);
    int tid = threadIdx.x;
    float s = 0.f, q = 0.f;
    for (int i = tid; i < CNT / 4; i += 256) {
        float4 v = p[i];
        s += v.x + v.y + v.z + v.w;
        q += v.x * v.x + v.y * v.y + v.z * v.z + v.w * v.w;
    }
    __shared__ float rs[256], rq[256];
    rs[tid] = s; rq[tid] = q;
    __syncthreads();
    for (int st2 = 128; st2 > 0; st2 >>= 1) {
        if (tid < st2) { rs[tid] += rs[tid + st2]; rq[tid] += rq[tid + st2]; }
        __syncthreads();
    }
    if (tid == 0) {
        float mean = rs[0] / 65536.f;
        float var  = rq[0] / 65536.f - mean * mean;
        st[blockIdx.x * 2 + 0] = mean;
        st[blockIdx.x * 2 + 1] = rsqrtf(var + 1e-6f);
    }
}

__global__ void gn_apply_kernel(const float* __restrict__ x,
                                const float* __restrict__ gamma,
                                const float* __restrict__ beta,
                                const float* __restrict__ st,
                                __nv_bfloat16* __restrict__ t) {
    __shared__ float tile[32][33];
    int b = blockIdx.z, n0 = blockIdx.x * 32, c0 = blockIdx.y * 32;
    int tx = threadIdx.x, ty = threadIdx.y;
#pragma unroll
    for (int i = 0; i < 4; i++) {
        int c = c0 + ty + i * 8;
        int g = c >> 4;
        float mean = st[(b * G_ + g) * 2 + 0];
        float rstd = st[(b * G_ + g) * 2 + 1];
        float v = x[((long)(b * C_ + c)) * N_ + n0 + tx];
        tile[ty + i * 8][tx] = (v - mean) * rstd * gamma[c] + beta[c];
    }
    __syncthreads();
#pragma unroll
    for (int i = 0; i < 4; i++) {
        int n = n0 + ty + i * 8;
        t[((long)b * N_ + n) * C_ + c0 + tx] = __float2bfloat16(tile[tx][ty + i * 8]);
    }
}

__global__ void f2b_kernel(const float* __restrict__ in,
                           __nv_bfloat16* __restrict__ out) {
    int i = (blockIdx.x * 256 + threadIdx.x) * 4;
    float4 v = *(const float4*)(in + i);
    __nv_bfloat162 p0 = __floats2bfloat162_rn(v.x, v.y);
    __nv_bfloat162 p1 = __floats2bfloat162_rn(v.z, v.w);
    *(uint2*)(out + i) = make_uint2(*reinterpret_cast<uint32_t*>(&p0),
                                    *reinterpret_cast<uint32_t*>(&p1));
}

// V [b,n,c] bf16 -> Vt [b,c,n] bf16
__global__ void vt_kernel(const __nv_bfloat16* __restrict__ v,
                          __nv_bfloat16* __restrict__ vt) {
    __shared__ __nv_bfloat16 tile[32][33];
    int b = blockIdx.z, n0 = blockIdx.x * 32, c0 = blockIdx.y * 32;
    int tx = threadIdx.x, ty = threadIdx.y;
#pragma unroll
    for (int i = 0; i < 4; i++) {
        int n = n0 + ty + i * 8;
        tile[ty + i * 8][tx] = v[((long)b * N_ + n) * C_ + c0 + tx];
    }
    __syncthreads();
#pragma unroll
    for (int i = 0; i < 4; i++) {
        int c = c0 + ty + i * 8;
        vt[((long)b * C_ + c) * N_ + n0 + tx] = tile[tx][ty + i * 8];
    }
}

// softmax over fp32 scores row -> bf16 probs
__global__ void softmax_kernel(const float* __restrict__ S,
                               __nv_bfloat16* __restrict__ P) {
    const float4* row = (const float4*)(S + ((long)blockIdx.y * N_ + blockIdx.x) * N_);
    __nv_bfloat16* prow = P + ((long)blockIdx.y * N_ + blockIdx.x) * N_;
    int tid = threadIdx.x;
    __shared__ float red[256];

    float m = -1e30f;
    for (int i = tid; i < N_ / 4; i += 256) {
        float4 v = row[i];
        m = fmaxf(m, fmaxf(fmaxf(v.x, v.y), fmaxf(v.z, v.w)));
    }
    red[tid] = m;
    __syncthreads();
    for (int s = 128; s > 0; s >>= 1) {
        if (tid < s) red[tid] = fmaxf(red[tid], red[tid + s]);
        __syncthreads();
    }
    m = red[0];
    __syncthreads();

    float sum = 0.f;
    for (int i = tid; i < N_ / 4; i += 256) {
        float4 v = row[i];
        sum += __expf(v.x - m) + __expf(v.y - m) + __expf(v.z - m) + __expf(v.w - m);
    }
    red[tid] = sum;
    __syncthreads();
    for (int s = 128; s > 0; s >>= 1) {
        if (tid < s) red[tid] += red[tid + s];
        __syncthreads();
    }
    float inv = 1.0f / red[0];

    for (int i = tid; i < N_ / 4; i += 256) {
        float4 v = row[i];
        __nv_bfloat162 p0 = __floats2bfloat162_rn(__expf(v.x - m) * inv, __expf(v.y - m) * inv);
        __nv_bfloat162 p1 = __floats2bfloat162_rn(__expf(v.z - m) * inv, __expf(v.w - m) * inv);
        *(uint2*)(prow + i * 4) = make_uint2(*reinterpret_cast<uint32_t*>(&p0),
                                             *reinterpret_cast<uint32_t*>(&p1));
    }
}

// out[b,c,n] = o2[b,n,c] + x[b,c,n]
__global__ void resid_kernel(const float* __restrict__ o2,
                             const float* __restrict__ x,
                             float* __restrict__ out) {
    __shared__ float tile[32][33];
    int b = blockIdx.z, n0 = blockIdx.x * 32, c0 = blockIdx.y * 32;
    int tx = threadIdx.x, ty = threadIdx.y;
#pragma unroll
    for (int i = 0; i < 4; i++) {
        int n = n0 + ty + i * 8;
        tile[ty + i * 8][tx] = o2[((long)b * N_ + n) * C_ + c0 + tx];
    }
    __syncthreads();
#pragma unroll
    for (int i = 0; i < 4; i++) {
        int c = c0 + ty + i * 8;
        long idx = ((long)(b * C_ + c)) * N_ + n0 + tx;
        out[idx] = tile[tx][ty + i * 8] + x[idx];
    }
}

// ======================= launcher ==========================================
extern "C" void kernel_launch(void* const* d_in, const int* in_sizes, int n_in,
                              void* d_out, int out_size) {
    const float* x     = (const float*)d_in[0];
    const float* gamma = (const float*)d_in[1];
    const float* beta  = (const float*)d_in[2];
    const float* wq_w  = (const float*)d_in[3];
    const float* wq_b  = (const float*)d_in[4];
    const float* wk_w  = (const float*)d_in[5];
    const float* wk_b  = (const float*)d_in[6];
    const float* wv_w  = (const float*)d_in[7];
    const float* wv_b  = (const float*)d_in[8];
    const float* ow_w  = (const float*)d_in[9];
    const float* ow_b  = (const float*)d_in[10];
    float* out = (float*)d_out;

    __nv_bfloat16 *t, *q, *k, *v, *vt, *o, *p, *w;
    float *s, *stats;
    cudaGetSymbolAddress((void**)&t,  gb_t);
    cudaGetSymbolAddress((void**)&q,  gb_q);
    cudaGetSymbolAddress((void**)&k,  gb_k);
    cudaGetSymbolAddress((void**)&v,  gb_v);
    cudaGetSymbolAddress((void**)&vt, gb_vt);
    cudaGetSymbolAddress((void**)&o,  gb_o);
    cudaGetSymbolAddress((void**)&p,  gb_p);
    cudaGetSymbolAddress((void**)&w,  gb_w);
    cudaGetSymbolAddress((void**)&s,  g_s);
    cudaGetSymbolAddress((void**)&stats, g_stats);

    const long tokS = (long)N_ * C_;
    const long scS  = (long)N_ * N_;
    const int  MT   = B_ * N_;           // 16384
    float* o2 = s;                       // reuse scores buffer for out-proj fp32

    // weight conversions (fp32 -> bf16)
    f2b_kernel<<<CC / 1024, 256>>>(wq_w, w + 0 * CC);
    f2b_kernel<<<CC / 1024, 256>>>(wk_w, w + 1 * CC);
    f2b_kernel<<<CC / 1024, 256>>>(wv_w, w + 2 * CC);
    f2b_kernel<<<CC / 1024, 256>>>(ow_w, w + 3 * CC);

    // GroupNorm
    gn_stats_kernel<<<B_ * G_, 256>>>(x, stats);
    gn_apply_kernel<<<dim3(N_ / 32, C_ / 32, B_), dim3(32, 8)>>>(x, gamma, beta, stats, t);

    // QKV projections: [16384,512] x [512,512]^T + bias -> bf16
    dim3 gproj(C_ / TN, MT / TM, 1);
    gemm_bf16_kernel<true><<<gproj, 256>>>(t, w + 0 * CC, q, C_, C_, 0, 0, 0, wq_b, 1.f);
    gemm_bf16_kernel<true><<<gproj, 256>>>(t, w + 1 * CC, k, C_, C_, 0, 0, 0, wk_b, 1.f);
    gemm_bf16_kernel<true><<<gproj, 256>>>(t, w + 2 * CC, v, C_, C_, 0, 0, 0, wv_b, 1.f);

    // V transpose -> [b,c,n]
    vt_kernel<<<dim3(N_ / 32, C_ / 32, B_), dim3(32, 8)>>>(v, vt);

    // scores = scale * Q K^T (batched) -> fp32
    gemm_bf16_kernel<false><<<dim3(N_ / TN, N_ / TM, B_), 256>>>(
        q, k, s, N_, C_, tokS, tokS, scS, nullptr, SCALE_);

    // softmax -> bf16 probs
    softmax_kernel<<<dim3(N_, B_), 256>>>(s, p);

    // O = P V : A = P [n,m], B = Vt [c,m] (NT, batched) -> bf16
    gemm_bf16_kernel<true><<<dim3(C_ / TN, N_ / TM, B_), 256>>>(
        p, vt, o, C_, N_, scS, tokS, tokS, nullptr, 1.f);

    // out projection + bias -> fp32 (into o2 = reused scores buffer)
    gemm_bf16_kernel<false><<<gproj, 256>>>(
        o, w + 3 * CC, o2, C_, C_, 0, 0, 0, ow_b, 1.f);

    // residual + transpose back to [b,c,h,w]
    resid_kernel<<<dim3(N_ / 32, C_ / 32, B_), dim3(32, 8)>>>(o2, x, out);
}

// round 7
// speedup vs baseline: 6.3794x; 1.2106x over previous
#include <cuda_runtime.h>
#include <cuda_bf16.h>
#include <stdint.h>

// ---------------------------------------------------------------------------
// SelfAttention: GroupNorm(32) -> QKV -> softmax(QK^T*s) V -> out proj -> +x
// b=4, c=512, h=w=64, N=4096. bf16 mma.sync m16n8k16 (fp32 accum), cp.async
// double-buffered BK=64, bf16 scores, fused V^T GEMM, register softmax.
// ---------------------------------------------------------------------------

#define B_ 4
#define C_ 512
#define N_ 4096
#define G_ 32
#define CPG 16
#define SCALE_ 0.044194173824159216f   // 1/sqrt(512)
#define CC (C_ * C_)

// ---------------- scratch (device globals; allocation-free) ----------------
__device__ __nv_bfloat16 gb_t [(long)B_ * N_ * C_];       // GN tokens [b,n,c]
__device__ __nv_bfloat16 gb_qk[(long)B_ * N_ * 2 * C_];   // [b,n, q(512)|k(512)]
__device__ __nv_bfloat16 gb_vt[(long)C_ * B_ * N_];       // V^T [c, b*N+n]
__device__ __nv_bfloat16 gb_o [(long)B_ * N_ * C_];       // attn out [b,n,c]
__device__ __nv_bfloat16 gb_s [(long)B_ * N_ * N_];       // scores/probs bf16
__device__ float         g_o2 [(long)B_ * N_ * C_];       // out-proj fp32
__device__ __nv_bfloat16 gb_w [4 * CC];                   // bf16 w: q,k,v,out
__device__ float         g_bias[2 * C_];                  // concat qb|kb
__device__ float         g_stats[B_ * G_ * 2];

// ======================= PTX helpers =======================================
__device__ __forceinline__ uint32_t smem_u32(const void* p) {
    uint32_t a;
    asm("{ .reg .u64 t; cvta.to.shared.u64 t, %1; cvt.u32.u64 %0, t; }"
        : "=r"(a) : "l"(p));
    return a;
}
__device__ __forceinline__ void ldm_x4(uint32_t* r, uint32_t addr) {
    asm volatile("ldmatrix.sync.aligned.m8n8.x4.shared.b16 {%0,%1,%2,%3}, [%4];"
                 : "=r"(r[0]), "=r"(r[1]), "=r"(r[2]), "=r"(r[3]) : "r"(addr));
}
__device__ __forceinline__ void mma16816(float* c, const uint32_t* a,
                                         const uint32_t* b) {
    asm volatile(
        "mma.sync.aligned.m16n8k16.row.col.f32.bf16.bf16.f32 "
        "{%0,%1,%2,%3}, {%4,%5,%6,%7}, {%8,%9}, {%0,%1,%2,%3};"
        : "+f"(c[0]), "+f"(c[1]), "+f"(c[2]), "+f"(c[3])
        : "r"(a[0]), "r"(a[1]), "r"(a[2]), "r"(a[3]), "r"(b[0]), "r"(b[1]));
}
__device__ __forceinline__ void cp16(uint32_t dst, const void* src) {
    asm volatile("cp.async.cg.shared.global [%0], [%1], 16;"
                 :: "r"(dst), "l"(src));
}
#define CP_COMMIT() asm volatile("cp.async.commit_group;" ::: "memory")
#define CP_WAIT(n)  asm volatile("cp.async.wait_group %0;" :: "n"(n) : "memory")

// ======================= bf16 mma.sync NT GEMM =============================
// D[M,Ncols] = scale * A[M,K] B[Ncols,K]^T (+bias per out col).
// Tiles: 128x128x64. 8 warps (64x32 each). SMEM rows padded to 144B.
#define TM 128
#define TN 128
#define TK 64
#define ROWB 144                       // bytes per padded smem row (128 data)
#define ATILE (TM * ROWB)              // 18432
#define SBUF  (2 * ATILE)              // one stage: A + B tiles
#define SMEM_DYN (2 * SBUF)            // 73728 (double buffered)

template <bool OBF>
__global__ __launch_bounds__(256, 2)
void gemm_bf16_kernel(const __nv_bfloat16* __restrict__ A,
                      const __nv_bfloat16* __restrict__ Bm,
                      void* __restrict__ Cout,
                      int lda, int ldb, int ldc, int K,
                      long sA, long sB, long sC,
                      const float* __restrict__ bias, float scale) {
    extern __shared__ char smem[];
    const uint32_t sb = smem_u32(smem);
    const int tid  = threadIdx.x;
    const int lane = tid & 31;
    const int wid  = tid >> 5;
    const int wm   = (wid & 1) * 64;      // warp m-offset
    const int wn   = (wid >> 1) * 32;     // warp n-offset

    const char* Ag = (const char*)(A  + (long)blockIdx.z * sA
                                      + (long)blockIdx.y * TM * lda);
    const char* Bg = (const char*)(Bm + (long)blockIdx.z * sB
                                      + (long)blockIdx.x * TN * ldb);
    const long ldab = (long)lda * 2;     // row strides in bytes
    const long ldbb = (long)ldb * 2;

    // tile loads: 1024 uint4 per operand tile, 4 per thread
    const int lr0 = tid >> 3;            // base row (steps of 32)
    const int lc0 = (tid & 7) * 16;      // byte col within 128-byte row
    const int nch = K / TK;

    {   // prologue: chunk 0 -> buffer 0
#pragma unroll
        for (int i = 0; i < 4; i++) {
            int r = lr0 + i * 32;
            cp16(sb + r * ROWB + lc0,         Ag + (long)r * ldab + lc0);
            cp16(sb + ATILE + r * ROWB + lc0, Bg + (long)r * ldbb + lc0);
        }
        CP_COMMIT();
    }

    float acc[4][4][4] = {};

    for (int c = 0; c < nch; c++) {
        const int buf = c & 1;
        if (c + 1 < nch) {
            const char* Ap = Ag + (long)(c + 1) * (TK * 2);
            const char* Bp = Bg + (long)(c + 1) * (TK * 2);
            const uint32_t d = sb + (buf ^ 1) * SBUF;
#pragma unroll
            for (int i = 0; i < 4; i++) {
                int r = lr0 + i * 32;
                cp16(d + r * ROWB + lc0,         Ap + (long)r * ldab + lc0);
                cp16(d + ATILE + r * ROWB + lc0, Bp + (long)r * ldbb + lc0);
            }
            CP_COMMIT();
            CP_WAIT(1);
        } else {
            CP_WAIT(0);
        }
        __syncthreads();

        const uint32_t Ab = sb + buf * SBUF;
        const uint32_t Bb = Ab + ATILE;
#pragma unroll
        for (int ks = 0; ks < 4; ks++) {
            const int kb = ks * 32;       // byte offset of k16 step
            uint32_t afr[4][4], bfr[4][2];
#pragma unroll
            for (int mi = 0; mi < 4; mi++) {
                int row = wm + mi * 16 + (lane & 15);
                ldm_x4(afr[mi], Ab + row * ROWB + kb + (lane >> 4) * 16);
            }
#pragma unroll
            for (int njp = 0; njp < 2; njp++) {
                uint32_t r4[4];
                int nrow = wn + njp * 16 + ((lane >> 4) * 8) + (lane & 7);
                int kbb  = kb + ((lane >> 3) & 1) * 16;
                ldm_x4(r4, Bb + nrow * ROWB + kbb);
                bfr[njp * 2 + 0][0] = r4[0]; bfr[njp * 2 + 0][1] = r4[1];
                bfr[njp * 2 + 1][0] = r4[2]; bfr[njp * 2 + 1][1] = r4[3];
            }
#pragma unroll
            for (int mi = 0; mi < 4; mi++)
#pragma unroll
                for (int nj = 0; nj < 4; nj++)
                    mma16816(acc[mi][nj], afr[mi], bfr[nj]);
        }
        __syncthreads();
    }

    // ---- epilogue ----
    const int bmr = blockIdx.y * TM + wm;
    const int bnc = blockIdx.x * TN + wn;
    const long cb = (long)blockIdx.z * sC;
#pragma unroll
    for (int mi = 0; mi < 4; mi++) {
#pragma unroll
        for (int h = 0; h < 2; h++) {
            const int row = bmr + mi * 16 + (lane >> 2) + 8 * h;
#pragma unroll
            for (int nj = 0; nj < 4; nj++) {
                const int col = bnc + nj * 8 + (lane & 3) * 2;
                float v0 = acc[mi][nj][2 * h + 0] * scale;
                float v1 = acc[mi][nj][2 * h + 1] * scale;
                if (bias) { v0 += __ldg(&bias[col]); v1 += __ldg(&bias[col + 1]); }
                if (OBF) {
                    __nv_bfloat162 bp = __floats2bfloat162_rn(v0, v1);
                    *(uint32_t*)((__nv_bfloat16*)Cout + cb + (long)row * ldc + col) =
                        *reinterpret_cast<uint32_t*>(&bp);
                } else {
                    *(float2*)((float*)Cout + cb + (long)row * ldc + col) =
                        make_float2(v0, v1);
                }
            }
        }
    }
}

// ======================= small kernels =====================================
__global__ void gn_stats_kernel(const float* __restrict__ x, float* __restrict__ st) {
    const long CNT = (long)CPG * N_;
    const float4* p = (const float4*)(x + (long)blockIdx.x * CNT);
    int tid = threadIdx.x;
    float s = 0.f, q = 0.f;
    for (int i = tid; i < CNT / 4; i += 256) {
        float4 v = p[i];
        s += v.x + v.y + v.z + v.w;
        q += v.x * v.x + v.y * v.y + v.z * v.z + v.w * v.w;
    }
    __shared__ float rs[256], rq[256];
    rs[tid] = s; rq[tid] = q;
    __syncthreads();
    for (int st2 = 128; st2 > 0; st2 >>= 1) {
        if (tid < st2) { rs[tid] += rs[tid + st2]; rq[tid] += rq[tid + st2]; }
        __syncthreads();
    }
    if (tid == 0) {
        float mean = rs[0] / 65536.f;
        float var  = rq[0] / 65536.f - mean * mean;
        st[blockIdx.x * 2 + 0] = mean;
        st[blockIdx.x * 2 + 1] = rsqrtf(var + 1e-6f);
    }
}

__global__ void gn_apply_kernel(const float* __restrict__ x,
                                const float* __restrict__ gamma,
                                const float* __restrict__ beta,
                                const float* __restrict__ st,
                                __nv_bfloat16* __restrict__ t) {
    __shared__ float tile[32][33];
    int b = blockIdx.z, n0 = blockIdx.x * 32, c0 = blockIdx.y * 32;
    int tx = threadIdx.x, ty = threadIdx.y;
#pragma unroll
    for (int i = 0; i < 4; i++) {
        int c = c0 + ty + i * 8;
        int g = c >> 4;
        float mean = st[(b * G_ + g) * 2 + 0];
        float rstd = st[(b * G_ + g) * 2 + 1];
        float v = x[((long)(b * C_ + c)) * N_ + n0 + tx];
        tile[ty + i * 8][tx] = (v - mean) * rstd * gamma[c] + beta[c];
    }
    __syncthreads();
#pragma unroll
    for (int i = 0; i < 4; i++) {
        int n = n0 + ty + i * 8;
        t[((long)b * N_ + n) * C_ + c0 + tx] = __float2bfloat16(tile[tx][ty + i * 8]);
    }
}

__global__ void f2b_kernel(const float* __restrict__ in,
                           __nv_bfloat16* __restrict__ out) {
    int i = (blockIdx.x * 256 + threadIdx.x) * 4;
    float4 v = *(const float4*)(in + i);
    __nv_bfloat162 p0 = __floats2bfloat162_rn(v.x, v.y);
    __nv_bfloat162 p1 = __floats2bfloat162_rn(v.z, v.w);
    *(uint2*)(out + i) = make_uint2(*reinterpret_cast<uint32_t*>(&p0),
                                    *reinterpret_cast<uint32_t*>(&p1));
}

// In-place softmax over a 4096-length bf16 row. Row cached in registers.
__global__ void softmax_kernel(__nv_bfloat16* __restrict__ S) {
    __nv_bfloat16* row = S + ((long)blockIdx.y * N_ + blockIdx.x) * N_;
    const int tid = threadIdx.x;
    uint4* rp = (uint4*)(row) + tid * 2;          // 16 bf16 per thread
    uint4 raw[2];
    raw[0] = rp[0]; raw[1] = rp[1];

    float v[16];
#pragma unroll
    for (int u = 0; u < 2; u++) {
        const uint32_t* w32 = (const uint32_t*)&raw[u];
#pragma unroll
        for (int j = 0; j < 4; j++) {
            __nv_bfloat162 b2 = *reinterpret_cast<const __nv_bfloat162*>(&w32[j]);
            float2 f2 = __bfloat1622float2(b2);
            v[u * 8 + j * 2 + 0] = f2.x;
            v[u * 8 + j * 2 + 1] = f2.y;
        }
    }

    __shared__ float red[256];
    float m = v[0];
#pragma unroll
    for (int j = 1; j < 16; j++) m = fmaxf(m, v[j]);
    red[tid] = m;
    __syncthreads();
    for (int s = 128; s > 0; s >>= 1) {
        if (tid < s) red[tid] = fmaxf(red[tid], red[tid + s]);
        __syncthreads();
    }
    m = red[0];
    __syncthreads();

    float sum = 0.f;
#pragma unroll
    for (int j = 0; j < 16; j++) { v[j] = __expf(v[j] - m); sum += v[j]; }
    red[tid] = sum;
    __syncthreads();
    for (int s = 128; s > 0; s >>= 1) {
        if (tid < s) red[tid] += red[tid + s];
        __syncthreads();
    }
    const float inv = 1.0f / red[0];

#pragma unroll
    for (int u = 0; u < 2; u++) {
        uint32_t* w32 = (uint32_t*)&raw[u];
#pragma unroll
        for (int j = 0; j < 4; j++) {
            __nv_bfloat162 b2 = __floats2bfloat162_rn(v[u * 8 + j * 2] * inv,
                                                      v[u * 8 + j * 2 + 1] * inv);
            w32[j] = *reinterpret_cast<uint32_t*>(&b2);
        }
    }
    rp[0] = raw[0]; rp[1] = raw[1];
}

// out[b,c,n] = o2[b,n,c] + x[b,c,n]
__global__ void resid_kernel(const float* __restrict__ o2,
                             const float* __restrict__ x,
                             float* __restrict__ out) {
    __shared__ float tile[32][33];
    int b = blockIdx.z, n0 = blockIdx.x * 32, c0 = blockIdx.y * 32;
    int tx = threadIdx.x, ty = threadIdx.y;
#pragma unroll
    for (int i = 0; i < 4; i++) {
        int n = n0 + ty + i * 8;
        tile[ty + i * 8][tx] = o2[((long)b * N_ + n) * C_ + c0 + tx];
    }
    __syncthreads();
#pragma unroll
    for (int i = 0; i < 4; i++) {
        int c = c0 + ty + i * 8;
        long idx = ((long)(b * C_ + c)) * N_ + n0 + tx;
        out[idx] = tile[tx][ty + i * 8] + x[idx];
    }
}

// ======================= launcher ==========================================
extern "C" void kernel_launch(void* const* d_in, const int* in_sizes, int n_in,
                              void* d_out, int out_size) {
    const float* x     = (const float*)d_in[0];
    const float* gamma = (const float*)d_in[1];
    const float* beta  = (const float*)d_in[2];
    const float* wq_w  = (const float*)d_in[3];
    const float* wq_b  = (const float*)d_in[4];
    const float* wk_w  = (const float*)d_in[5];
    const float* wk_b  = (const float*)d_in[6];
    const float* wv_w  = (const float*)d_in[7];
    const float* wv_b  = (const float*)d_in[8];
    const float* ow_w  = (const float*)d_in[9];
    const float* ow_b  = (const float*)d_in[10];
    float* out = (float*)d_out;

    __nv_bfloat16 *t, *qk, *vt, *o, *s, *w;
    float *o2, *bias2, *stats;
    cudaGetSymbolAddress((void**)&t,  gb_t);
    cudaGetSymbolAddress((void**)&qk, gb_qk);
    cudaGetSymbolAddress((void**)&vt, gb_vt);
    cudaGetSymbolAddress((void**)&o,  gb_o);
    cudaGetSymbolAddress((void**)&s,  gb_s);
    cudaGetSymbolAddress((void**)&w,  gb_w);
    cudaGetSymbolAddress((void**)&o2, g_o2);
    cudaGetSymbolAddress((void**)&bias2, g_bias);
    cudaGetSymbolAddress((void**)&stats, g_stats);

    cudaFuncSetAttribute(gemm_bf16_kernel<true>,
                         cudaFuncAttributeMaxDynamicSharedMemorySize, SMEM_DYN);
    cudaFuncSetAttribute(gemm_bf16_kernel<false>,
                         cudaFuncAttributeMaxDynamicSharedMemorySize, SMEM_DYN);

    const int  MT   = B_ * N_;                 // 16384 tokens
    const long scS  = (long)N_ * N_;           // per-batch scores stride
    const long qkS  = (long)N_ * 2 * C_;       // per-batch qk stride
    const long oS   = (long)N_ * C_;

    // weight conversions (fp32 -> bf16); wq|wk concat occupies w[0..2CC)
    f2b_kernel<<<CC / 1024, 256>>>(wq_w, w + 0 * CC);
    f2b_kernel<<<CC / 1024, 256>>>(wk_w, w + 1 * CC);
    f2b_kernel<<<CC / 1024, 256>>>(wv_w, w + 2 * CC);
    f2b_kernel<<<CC / 1024, 256>>>(ow_w, w + 3 * CC);
    // concat q|k bias
    cudaMemcpyAsync(bias2,       wq_b, C_ * sizeof(float), cudaMemcpyDeviceToDevice);
    cudaMemcpyAsync(bias2 + C_,  wk_b, C_ * sizeof(float), cudaMemcpyDeviceToDevice);

    // GroupNorm
    gn_stats_kernel<<<B_ * G_, 256>>>(x, stats);
    gn_apply_kernel<<<dim3(N_ / 32, C_ / 32, B_), dim3(32, 8)>>>(x, gamma, beta, stats, t);

    // QK projection (merged): [16384,512] x [1024,512]^T + bias -> qk bf16
    gemm_bf16_kernel<true><<<dim3(2 * C_ / TN, MT / TM), 256, SMEM_DYN>>>(
        t, w, qk, C_, C_, 2 * C_, C_, 0, 0, 0, bias2, 1.f);

    // V^T: Vt[c, g] = wv[c,:] . t[g,:]  ->  [512, 16384] bf16 (no bias here)
    gemm_bf16_kernel<true><<<dim3(MT / TN, C_ / TM), 256, SMEM_DYN>>>(
        w + 2 * CC, t, vt, C_, C_, MT, C_, 0, 0, 0, nullptr, 1.f);

    // scores = scale * Q K^T (batched) -> bf16, in gb_s
    gemm_bf16_kernel<true><<<dim3(N_ / TN, N_ / TM, B_), 256, SMEM_DYN>>>(
        qk, qk + C_, s, 2 * C_, 2 * C_, N_, C_, qkS, qkS, scS, nullptr, SCALE_);

    // softmax in place (bf16)
    softmax_kernel<<<dim3(N_, B_), 256>>>(s);

    // O = P V + vb : A = P [n,m], B = Vt rows c, cols m (batch col-offset)
    gemm_bf16_kernel<true><<<dim3(C_ / TN, N_ / TM, B_), 256, SMEM_DYN>>>(
        s, vt, o, N_, MT, C_, N_, scS, (long)N_, oS, wv_b, 1.f);

    // out projection + bias -> fp32
    gemm_bf16_kernel<false><<<dim3(C_ / TN, MT / TM), 256, SMEM_DYN>>>(
        o, w + 3 * CC, o2, C_, C_, C_, C_, 0, 0, 0, ow_b, 1.f);

    // residual + transpose back to [b,c,h,w]
    resid_kernel<<<dim3(N_ / 32, C_ / 32, B_), dim3(32, 8)>>>(o2, x, out);
}